// round 4
// baseline (speedup 1.0000x reference)
#include <cuda_runtime.h>
#include <cstdint>

// ---------------------------------------------------------------------------
// GRU_2602750181500: bidirectional GRU, T=2048, B=32, F=H=512, fp32.
// Kernel 1: gi = x @ w_ih^T + b_ih (both dirs), fp32 FFMA2 GEMM.
// Kernel 2: persistent recurrence as 8 clusters of 16 CTAs (one cluster per
//   (dir, batch-group)). h exchanged via DSMEM push (st.shared::cluster) +
//   split cluster barriers. No L2 flags, no fences, no per-step L2 h copy.
//   h_old lives in a register per thread.
// ---------------------------------------------------------------------------

#define T_ 2048
#define B_ 32
#define H_ 512
#define G_ 1536

typedef unsigned long long ull;

__device__ __forceinline__ ull pkf(float lo, float hi) {
    ull r; asm("mov.b64 %0, {%1, %2};" : "=l"(r) : "f"(lo), "f"(hi)); return r;
}
__device__ __forceinline__ void fma2(ull& d, ull a, ull b) {
    asm("fma.rn.f32x2 %0, %1, %2, %0;" : "+l"(d) : "l"(a), "l"(b));
}
__device__ __forceinline__ float2 upk(ull v) {
    float2 f; asm("mov.b64 {%0, %1}, %2;" : "=f"(f.x), "=f"(f.y) : "l"(v)); return f;
}

#define CLUSTER_ARRIVE() asm volatile("barrier.cluster.arrive.aligned;" ::: "memory")
#define CLUSTER_WAIT()   asm volatile("barrier.cluster.wait.aligned;"   ::: "memory")

__device__ __forceinline__ uint32_t smem_u32(const void* p) {
    uint32_t a;
    asm("{ .reg .u64 t; cvta.to.shared.u64 t, %1; cvt.u32.u64 %0, t; }"
        : "=r"(a) : "l"(p));
    return a;
}
__device__ __forceinline__ uint32_t mapa_rank(uint32_t laddr, int rank) {
    uint32_t r;
    asm("mapa.shared::cluster.u32 %0, %1, %2;" : "=r"(r) : "r"(laddr), "r"(rank));
    return r;
}
__device__ __forceinline__ void st_dsmem_v4(uint32_t addr, float4 v) {
    asm volatile("st.shared::cluster.v4.b32 [%0], {%1, %2, %3, %4};"
                 :: "r"(addr), "f"(v.x), "f"(v.y), "f"(v.z), "f"(v.w) : "memory");
}

// Scratch (device global: allocation-free rule).
__device__ float g_gi[2][(size_t)T_ * B_ * G_];   // [dir][t*B+b][3H]

// ---------------------------------------------------------------------------
// Kernel 1: gi GEMM (FFMA2, unchanged from R3).
// ---------------------------------------------------------------------------
__global__ void __launch_bounds__(256, 2) gi_gemm(
    const float* __restrict__ x,
    const float* __restrict__ wf, const float* __restrict__ bf,
    const float* __restrict__ wr, const float* __restrict__ br)
{
    __shared__ float Xs[8][132];
    __shared__ float Ws[8][132];

    const int tid = threadIdx.x;
    const int dir = blockIdx.z;
    const float* __restrict__ w    = dir ? wr : wf;
    const float* __restrict__ bias = dir ? br : bf;
    float* __restrict__ gi = g_gi[dir];

    const int m0 = blockIdx.y * 128;
    const int n0 = blockIdx.x * 128;

    const int lr = tid >> 1;
    const int lc = (tid & 1) * 4;

    const float* xg = x + (size_t)(m0 + lr) * 512 + lc;
    const float* wg = w + (size_t)(n0 + lr) * 512 + lc;

    const int tx = tid & 15, ty = tid >> 4;

    ull acc[8][4];
#pragma unroll
    for (int i = 0; i < 8; i++)
#pragma unroll
        for (int j = 0; j < 4; j++) acc[i][j] = 0ULL;

    float4 xa = *(const float4*)xg;
    float4 wa = *(const float4*)wg;

    for (int kt = 0; kt < 512; kt += 8) {
        Xs[lc + 0][lr] = xa.x; Xs[lc + 1][lr] = xa.y;
        Xs[lc + 2][lr] = xa.z; Xs[lc + 3][lr] = xa.w;
        Ws[lc + 0][lr] = wa.x; Ws[lc + 1][lr] = wa.y;
        Ws[lc + 2][lr] = wa.z; Ws[lc + 3][lr] = wa.w;
        __syncthreads();
        if (kt + 8 < 512) {
            xa = *(const float4*)(xg + kt + 8);
            wa = *(const float4*)(wg + kt + 8);
        }
#pragma unroll
        for (int kk = 0; kk < 8; kk++) {
            float4 a0 = *(const float4*)&Xs[kk][ty * 8];
            float4 a1 = *(const float4*)&Xs[kk][ty * 8 + 4];
            float4 b0 = *(const float4*)&Ws[kk][tx * 8];
            float4 b1 = *(const float4*)&Ws[kk][tx * 8 + 4];
            ull bq[4] = { pkf(b0.x, b0.y), pkf(b0.z, b0.w),
                          pkf(b1.x, b1.y), pkf(b1.z, b1.w) };
            float av[8] = { a0.x, a0.y, a0.z, a0.w, a1.x, a1.y, a1.z, a1.w };
#pragma unroll
            for (int i = 0; i < 8; i++) {
                ull aq = pkf(av[i], av[i]);
#pragma unroll
                for (int j = 0; j < 4; j++) fma2(acc[i][j], aq, bq[j]);
            }
        }
        __syncthreads();
    }

    float bb2[8];
#pragma unroll
    for (int j = 0; j < 8; j++) bb2[j] = bias[n0 + tx * 8 + j];
#pragma unroll
    for (int i = 0; i < 8; i++) {
        float* cp = gi + (size_t)(m0 + ty * 8 + i) * G_ + n0 + tx * 8;
#pragma unroll
        for (int j = 0; j < 4; j++) {
            float2 v = upk(acc[i][j]);
            v.x += bb2[2 * j]; v.y += bb2[2 * j + 1];
            *(float2*)(cp + 2 * j) = v;
        }
    }
}

// ---------------------------------------------------------------------------
// Kernel 2: recurrence, 8 clusters x 16 CTAs.
// SMEM: w [96][516] | sh [512][8] | sgh [96][17] | sgi [768] | sstage [256]
// ---------------------------------------------------------------------------
#define SW_STRIDE 516
#define OFF_H    (96 * SW_STRIDE)        // 49536
#define OFF_GH   (OFF_H + 512 * 8)       // 53632
#define OFF_GI   (OFF_GH + 96 * 17)      // 55264
#define OFF_ST   (OFF_GI + 768)          // 56032
#define SMEM_TOT (OFF_ST + 256)          // 56288 floats = 225152 B
#define SMEM_REC (SMEM_TOT * 4)

__global__ void __launch_bounds__(256, 1) gru_rec(
    const float* __restrict__ h0,
    const float* __restrict__ whh_f, const float* __restrict__ bhh_f,
    const float* __restrict__ whh_r, const float* __restrict__ bhh_r,
    float* __restrict__ out, int out_size)
{
    extern __shared__ float smem[];
    float* sw  = smem;              // [96][516]
    float* sh  = smem + OFF_H;      // [512][8] : h for this bgroup
    float* sgh = smem + OFF_GH;     // [96][17]
    float* sgi = smem + OFF_GI;     // [8 batch][3 gate][32]
    float* sst = smem + OFF_ST;     // [256] hn staging (chunk-local layout)

    const int tid = threadIdx.x;
    const int bid = blockIdx.x;
    const int dir = bid >> 6;
    const int bg  = (bid >> 4) & 3;
    const int sl  = bid & 15;       // == cluster rank

    const float* __restrict__ whh = dir ? whh_r : whh_f;
    const float* __restrict__ bhh = dir ? bhh_r : bhh_f;
    const float* __restrict__ gi  = g_gi[dir];

    // Load 96 w_hh rows into SMEM (once).
    for (int idx = tid; idx < 96 * 128; idx += 256) {
        int r = idx >> 7, c4 = (idx & 127) << 2;
        int gate = r >> 5, il2 = r & 31;
        float4 v = *(const float4*)&whh[(size_t)((gate << 9) + sl * 32 + il2) * 512 + c4];
        *(float4*)&sw[r * SW_STRIDE + c4] = v;
    }

    // Init sh with full h(0) for this bgroup.
    for (int i = tid; i < 4096; i += 256) {
        int k = i >> 3, b2 = i & 7;
        sh[i] = h0[(size_t)(dir * B_ + bg * 8 + b2) * H_ + k];
    }

    const int b  = tid >> 5;        // batch within group
    const int il = tid & 31;        // hidden within slice
    const int iglob = sl * 32 + il;
    const int bglob = bg * 8 + b;

    float hold = h0[(size_t)(dir * B_ + bglob) * H_ + iglob];

    const float bh_r = bhh[iglob];
    const float bh_z = bhh[512 + iglob];
    const float bh_n = bhh[1024 + iglob];

    // Scatter setup: thread t pushes 4 float4s of this CTA's chunk, one to
    // each of 4 ranks; chunk lives at sh[sl*256 .. sl*256+256).
    const uint32_t sh_addr = smem_u32(sh);
    uint32_t raddr[4];
    int      soff[4];
#pragma unroll
    for (int i = 0; i < 4; i++) {
        int g = tid + 256 * i;          // 0..1023
        int rank = g >> 6;              // 0..15
        soff[i] = (g & 63) * 4;         // float offset within 1KB chunk
        raddr[i] = mapa_rank(sh_addr + (uint32_t)(sl * 256 + soff[i]) * 4u, rank);
    }

    __syncthreads();
    CLUSTER_ARRIVE();                   // phase: h(0) ready (local init)

    // GEMV mapping: tid<192 -> r = tid%96, kh = tid/96 (warp-uniform kh).
    const int r   = tid % 96;
    const int kh  = tid / 96;
    const int j0  = tid - 192;

    const bool write_states = (out_size > T_ * B_ * 2 * H_);

    for (int s = 0; s < T_; s++) {
        const int xrow = dir ? (T_ - 1 - s) : s;

        // gi prefetch (warps 6-7): LDG before the barrier wait.
        float4 gv0, gv1, gv2;
        if (tid >= 192) {
            const float* gbase = gi + ((size_t)xrow * B_ + bg * 8) * G_ + sl * 32;
#pragma unroll
            for (int i = 0; i < 3; i++) {
                int j = j0 + 64 * i;
                int b2 = j / 24, rem = j % 24, g = rem >> 3, q = rem & 7;
                float4 v = __ldcs((const float4*)(gbase + (size_t)b2 * G_ + g * 512 + q * 4));
                if (i == 0) gv0 = v; else if (i == 1) gv1 = v; else gv2 = v;
            }
        }

        CLUSTER_WAIT();                 // h(s) fully scattered into sh

        if (tid < 192) {
            const float* wp = sw + r * SW_STRIDE + kh * 256;
            const ull*   hp = (const ull*)(sh + kh * 256 * 8);
            ull a0 = 0, a1 = 0, a2 = 0, a3 = 0;
#pragma unroll 2
            for (int k = 0; k < 256; k += 4) {
                float4 w4 = *(const float4*)(wp + k);
                {
                    ull wq = pkf(w4.x, w4.x);
                    ulonglong2 hA = *(const ulonglong2*)(hp + (size_t)(k + 0) * 4);
                    ulonglong2 hB = *(const ulonglong2*)(hp + (size_t)(k + 0) * 4 + 2);
                    fma2(a0, wq, hA.x); fma2(a1, wq, hA.y);
                    fma2(a2, wq, hB.x); fma2(a3, wq, hB.y);
                }
                {
                    ull wq = pkf(w4.y, w4.y);
                    ulonglong2 hA = *(const ulonglong2*)(hp + (size_t)(k + 1) * 4);
                    ulonglong2 hB = *(const ulonglong2*)(hp + (size_t)(k + 1) * 4 + 2);
                    fma2(a0, wq, hA.x); fma2(a1, wq, hA.y);
                    fma2(a2, wq, hB.x); fma2(a3, wq, hB.y);
                }
                {
                    ull wq = pkf(w4.z, w4.z);
                    ulonglong2 hA = *(const ulonglong2*)(hp + (size_t)(k + 2) * 4);
                    ulonglong2 hB = *(const ulonglong2*)(hp + (size_t)(k + 2) * 4 + 2);
                    fma2(a0, wq, hA.x); fma2(a1, wq, hA.y);
                    fma2(a2, wq, hB.x); fma2(a3, wq, hB.y);
                }
                {
                    ull wq = pkf(w4.w, w4.w);
                    ulonglong2 hA = *(const ulonglong2*)(hp + (size_t)(k + 3) * 4);
                    ulonglong2 hB = *(const ulonglong2*)(hp + (size_t)(k + 3) * 4 + 2);
                    fma2(a0, wq, hA.x); fma2(a1, wq, hA.y);
                    fma2(a2, wq, hB.x); fma2(a3, wq, hB.y);
                }
            }
            float* gdst = sgh + r * 17 + kh * 8;
            float2 p;
            p = upk(a0); gdst[0] = p.x; gdst[1] = p.y;
            p = upk(a1); gdst[2] = p.x; gdst[3] = p.y;
            p = upk(a2); gdst[4] = p.x; gdst[5] = p.y;
            p = upk(a3); gdst[6] = p.x; gdst[7] = p.y;
        } else {
#pragma unroll
            for (int i = 0; i < 3; i++) {
                int j = j0 + 64 * i;
                int b2 = j / 24, rem = j % 24, g = rem >> 3, q = rem & 7;
                float4 v = (i == 0) ? gv0 : (i == 1) ? gv1 : gv2;
                *(float4*)&sgi[(b2 * 3 + g) * 32 + q * 4] = v;
            }
        }
        __syncthreads();
        CLUSTER_ARRIVE();               // done reading sh (h(s))

        // Epilogue (all 256 threads; h_old from register).
        const float gir = sgi[(b * 3 + 0) * 32 + il];
        const float giz = sgi[(b * 3 + 1) * 32 + il];
        const float gin = sgi[(b * 3 + 2) * 32 + il];

        const float ghr = sgh[il * 17 + b]        + sgh[il * 17 + 8 + b]        + bh_r;
        const float ghz = sgh[(32 + il) * 17 + b] + sgh[(32 + il) * 17 + 8 + b] + bh_z;
        const float ghn = sgh[(64 + il) * 17 + b] + sgh[(64 + il) * 17 + 8 + b] + bh_n;

        const float rg = 1.f / (1.f + __expf(-(gir + ghr)));
        const float zg = 1.f / (1.f + __expf(-(giz + ghz)));
        const float ng = tanhf(gin + rg * ghn);
        const float hn = (1.f - zg) * ng + zg * hold;
        hold = hn;

        sst[il * 8 + b] = hn;           // chunk-local layout (matches sh chunk)
        __syncthreads();
        CLUSTER_WAIT();                 // all CTAs done reading h(s) -> safe to overwrite sh

        // DSMEM push: this CTA's 1KB hn-chunk to all 16 CTAs' sh.
#pragma unroll
        for (int i = 0; i < 4; i++) {
            float4 v = *(const float4*)&sst[soff[i]];
            st_dsmem_v4(raddr[i], v);
        }
        CLUSTER_ARRIVE();               // h(s+1) ready (release covers DSMEM stores)

        // Off critical path: global output stores.
        out[((size_t)s * B_ + bglob) * (2 * H_) + dir * H_ + iglob] = hn;
        if (write_states && s == T_ - 1)
            out[(size_t)T_ * B_ * 2 * H_ + (size_t)(dir * B_ + bglob) * H_ + iglob] = hn;
    }
}

// ---------------------------------------------------------------------------
extern "C" void kernel_launch(void* const* d_in, const int* in_sizes, int n_in,
                              void* d_out, int out_size)
{
    const float* x    = (const float*)d_in[0];
    const float* h0   = (const float*)d_in[1];
    const float* wihf = (const float*)d_in[2];
    const float* bihf = (const float*)d_in[3];
    const float* whhf = (const float*)d_in[4];
    const float* bhhf = (const float*)d_in[5];
    const float* wihr = (const float*)d_in[6];
    const float* bihr = (const float*)d_in[7];
    const float* whhr = (const float*)d_in[8];
    const float* bhhr = (const float*)d_in[9];
    float* out = (float*)d_out;

    cudaFuncSetAttribute(gru_rec, cudaFuncAttributeMaxDynamicSharedMemorySize, SMEM_REC);
    cudaFuncSetAttribute(gru_rec, cudaFuncAttributeNonPortableClusterSizeAllowed, 1);

    dim3 g1(G_ / 128, (T_ * B_) / 128, 2);
    gi_gemm<<<g1, 256>>>(x, wihf, bihf, wihr, bihr);

    cudaLaunchConfig_t cfg = {};
    cfg.gridDim  = dim3(128, 1, 1);
    cfg.blockDim = dim3(256, 1, 1);
    cfg.dynamicSmemBytes = SMEM_REC;
    cudaLaunchAttribute attrs[1];
    attrs[0].id = cudaLaunchAttributeClusterDimension;
    attrs[0].val.clusterDim = {16, 1, 1};
    cfg.attrs = attrs;
    cfg.numAttrs = 1;
    cudaLaunchKernelEx(&cfg, gru_rec, h0, whhf, bhhf, whhr, bhhr, out, out_size);
}

// round 5
// speedup vs baseline: 1.7760x; 1.7760x over previous
#include <cuda_runtime.h>
#include <cstdint>

// ---------------------------------------------------------------------------
// GRU_2602750181500: bidirectional GRU, T=2048, B=32, F=H=512, fp32.
// Kernel 1: gi = x @ w_ih^T + b_ih (both dirs), fp32 FFMA2 GEMM.
// Kernel 2: persistent recurrence, 128 blocks = 2 dirs x 4 bgroups x 16 slices.
//   R5: GEMV rebuilt for LDS economy — 8 warps, warp=k-chunk, 3 rows/lane,
//   conflict-free w (stride 513) + broadcast h; 2-stage partial reduction.
//   Sync = R3's proven volatile flags + threadfence + nanosleep.
// ---------------------------------------------------------------------------

#define T_ 2048
#define B_ 32
#define H_ 512
#define G_ 1536

typedef unsigned long long ull;

__device__ __forceinline__ ull pkf(float lo, float hi) {
    ull r; asm("mov.b64 %0, {%1, %2};" : "=l"(r) : "f"(lo), "f"(hi)); return r;
}
__device__ __forceinline__ void fma2(ull& d, ull a, ull b) {
    asm("fma.rn.f32x2 %0, %1, %2, %0;" : "+l"(d) : "l"(a), "l"(b));
}
__device__ __forceinline__ float2 upk(ull v) {
    float2 f; asm("mov.b64 {%0, %1}, %2;" : "=f"(f.x), "=f"(f.y) : "l"(v)); return f;
}

// Scratch (device globals: allocation-free rule).
__device__ float    g_gi[2][(size_t)T_ * B_ * G_];   // [dir][t*B+b][3H]
__device__ float    g_h[2][4][2][H_ * 8];            // [dir][bgroup][pingpong][k*8+b]
__device__ unsigned g_flags[2][4][16 * 8];           // [dir][bgroup][slice*8]

// ---------------------------------------------------------------------------
// Kernel 1: gi GEMM (FFMA2, unchanged).
// ---------------------------------------------------------------------------
__global__ void __launch_bounds__(256, 2) gi_gemm(
    const float* __restrict__ x,
    const float* __restrict__ wf, const float* __restrict__ bf,
    const float* __restrict__ wr, const float* __restrict__ br)
{
    __shared__ float Xs[8][132];
    __shared__ float Ws[8][132];

    const int tid = threadIdx.x;
    const int dir = blockIdx.z;
    const float* __restrict__ w    = dir ? wr : wf;
    const float* __restrict__ bias = dir ? br : bf;
    float* __restrict__ gi = g_gi[dir];

    const int m0 = blockIdx.y * 128;
    const int n0 = blockIdx.x * 128;

    const int lr = tid >> 1;
    const int lc = (tid & 1) * 4;

    const float* xg = x + (size_t)(m0 + lr) * 512 + lc;
    const float* wg = w + (size_t)(n0 + lr) * 512 + lc;

    const int tx = tid & 15, ty = tid >> 4;

    ull acc[8][4];
#pragma unroll
    for (int i = 0; i < 8; i++)
#pragma unroll
        for (int j = 0; j < 4; j++) acc[i][j] = 0ULL;

    float4 xa = *(const float4*)xg;
    float4 wa = *(const float4*)wg;

    for (int kt = 0; kt < 512; kt += 8) {
        Xs[lc + 0][lr] = xa.x; Xs[lc + 1][lr] = xa.y;
        Xs[lc + 2][lr] = xa.z; Xs[lc + 3][lr] = xa.w;
        Ws[lc + 0][lr] = wa.x; Ws[lc + 1][lr] = wa.y;
        Ws[lc + 2][lr] = wa.z; Ws[lc + 3][lr] = wa.w;
        __syncthreads();
        if (kt + 8 < 512) {
            xa = *(const float4*)(xg + kt + 8);
            wa = *(const float4*)(wg + kt + 8);
        }
#pragma unroll
        for (int kk = 0; kk < 8; kk++) {
            float4 a0 = *(const float4*)&Xs[kk][ty * 8];
            float4 a1 = *(const float4*)&Xs[kk][ty * 8 + 4];
            float4 b0 = *(const float4*)&Ws[kk][tx * 8];
            float4 b1 = *(const float4*)&Ws[kk][tx * 8 + 4];
            ull bq[4] = { pkf(b0.x, b0.y), pkf(b0.z, b0.w),
                          pkf(b1.x, b1.y), pkf(b1.z, b1.w) };
            float av[8] = { a0.x, a0.y, a0.z, a0.w, a1.x, a1.y, a1.z, a1.w };
#pragma unroll
            for (int i = 0; i < 8; i++) {
                ull aq = pkf(av[i], av[i]);
#pragma unroll
                for (int j = 0; j < 4; j++) fma2(acc[i][j], aq, bq[j]);
            }
        }
        __syncthreads();
    }

    float bb2[8];
#pragma unroll
    for (int j = 0; j < 8; j++) bb2[j] = bias[n0 + tx * 8 + j];
#pragma unroll
    for (int i = 0; i < 8; i++) {
        float* cp = gi + (size_t)(m0 + ty * 8 + i) * G_ + n0 + tx * 8;
#pragma unroll
        for (int j = 0; j < 4; j++) {
            float2 v = upk(acc[i][j]);
            v.x += bb2[2 * j]; v.y += bb2[2 * j + 1];
            *(float2*)(cp + 2 * j) = v;
        }
    }
}

// ---------------------------------------------------------------------------
// Kernel 2: persistent recurrence.
// SMEM: sw [96][513] | sh [512][8] | sgh [4][8][97]
// ---------------------------------------------------------------------------
#define SW2      513
#define OFF_H    (96 * SW2)              // 49248
#define OFF_GH   (OFF_H + 512 * 8)       // 53344
#define SMEM_TOT (OFF_GH + 4 * 776)      // 56448 floats = 225792 B
#define SMEM_REC (SMEM_TOT * 4)

__global__ void __launch_bounds__(256, 1) gru_rec(
    const float* __restrict__ h0,
    const float* __restrict__ whh_f, const float* __restrict__ bhh_f,
    const float* __restrict__ whh_r, const float* __restrict__ bhh_r,
    float* __restrict__ out, int out_size)
{
    extern __shared__ float smem[];
    float* sw  = smem;              // [96 r][513]  (r = gate*32 + il)
    float* sh  = smem + OFF_H;      // [512 k][8 b]
    float* sgh = smem + OFF_GH;     // [4 khp][8 b][97] partial gh

    const int tid  = threadIdx.x;
    const int warp = tid >> 5;
    const int lane = tid & 31;
    const int bid = blockIdx.x;
    const int dir = bid >> 6;
    const int bg  = (bid >> 4) & 3;
    const int sl  = bid & 15;

    const float* __restrict__ whh = dir ? whh_r : whh_f;
    const float* __restrict__ bhh = dir ? bhh_r : bhh_f;
    const float* __restrict__ gi  = g_gi[dir];
    volatile unsigned* flags = &g_flags[dir][bg][0];
    const unsigned base = flags[sl * 8];

    // Load 96 w_hh rows into SMEM (stride 513: bank = row + k, conflict-free).
    for (int idx = tid; idx < 96 * 128; idx += 256) {
        int r = idx >> 7, c4 = (idx & 127) << 2;
        int gate = r >> 5, il2 = r & 31;
        float4 v = *(const float4*)&whh[(size_t)((gate << 9) + sl * 32 + il2) * 512 + c4];
        float* d = &sw[r * SW2 + c4];
        d[0] = v.x; d[1] = v.y; d[2] = v.z; d[3] = v.w;
    }

    // Epilogue mapping: b == warp, il == lane.
    const int il = lane;
    const int iglob = sl * 32 + il;
    const int bglob = bg * 8 + warp;

    float* hbuf0 = g_h[dir][bg][0];
    float* hbuf1 = g_h[dir][bg][1];

    float hold = h0[(size_t)(dir * B_ + bglob) * H_ + iglob];
    hbuf0[iglob * 8 + warp] = hold;

    const float bh_r = bhh[iglob];
    const float bh_z = bhh[512 + iglob];
    const float bh_n = bhh[1024 + iglob];

    __syncthreads();
    __threadfence();
    if (tid == 0) flags[sl * 8] = base + 1;

    const bool write_states = (out_size > T_ * B_ * 2 * H_);

    // GEMV pointers: warp = k-chunk (64 k), lane = base row (3 rows/thread).
    const float* wp0 = sw + lane * SW2 + warp * 64;
    const float* wp1 = wp0 + 32 * SW2;
    const float* wp2 = wp0 + 64 * SW2;

    for (int s = 0; s < T_; s++) {
        const int xrow = dir ? (T_ - 1 - s) : s;

        // gi for this thread's epilogue element — issue LDGs before the poll.
        const float* gp = gi + ((size_t)xrow * B_ + bglob) * G_ + iglob;
        const float gir = __ldcs(gp);
        const float giz = __ldcs(gp + 512);
        const float gin = __ldcs(gp + 1024);

        // Acquire: all 16 slice blocks must have published h(s).
        if (tid < 16) {
            const unsigned target = base + 1 + (unsigned)s;
            while (flags[tid * 8] < target) __nanosleep(40);
        }
        __syncthreads();
        __threadfence();

        const float* hsrc = (s & 1) ? hbuf1 : hbuf0;
        float*       hdst = (s & 1) ? hbuf0 : hbuf1;

        // Load full h (512x8 = 16KB) into SMEM, L2-sourced.
        for (int idx = tid; idx < 1024; idx += 256)
            *(float4*)&sh[idx * 4] = __ldcg((const float4*)hsrc + idx);
        __syncthreads();

        // GEMV: 3 rows x 8 batches x 64 k per thread. 12 FFMA2 per k.
        ull a0[4], a1[4], a2[4];
#pragma unroll
        for (int j = 0; j < 4; j++) { a0[j] = 0; a1[j] = 0; a2[j] = 0; }

        const ull* hp = (const ull*)sh + (size_t)warp * 64 * 4;
#pragma unroll 4
        for (int kk = 0; kk < 64; kk++) {
            const float w0 = wp0[kk];
            const float w1 = wp1[kk];
            const float w2 = wp2[kk];
            ulonglong2 hA = *(const ulonglong2*)(hp + (size_t)kk * 4);
            ulonglong2 hB = *(const ulonglong2*)(hp + (size_t)kk * 4 + 2);
            const ull q0 = pkf(w0, w0);
            fma2(a0[0], q0, hA.x); fma2(a0[1], q0, hA.y);
            fma2(a0[2], q0, hB.x); fma2(a0[3], q0, hB.y);
            const ull q1 = pkf(w1, w1);
            fma2(a1[0], q1, hA.x); fma2(a1[1], q1, hA.y);
            fma2(a1[2], q1, hB.x); fma2(a1[3], q1, hB.y);
            const ull q2 = pkf(w2, w2);
            fma2(a2[0], q2, hA.x); fma2(a2[1], q2, hA.y);
            fma2(a2[2], q2, hB.x); fma2(a2[3], q2, hB.y);
        }

        // Stage 1: warps 0-3 store partials. sgh[khp][b][97]: bank=lane-distinct.
        float* sb = sgh + (warp & 3) * 776;
        if (warp < 4) {
#pragma unroll
            for (int j = 0; j < 4; j++) {
                float2 p;
                p = upk(a0[j]);
                sb[(2 * j) * 97 + lane]          = p.x;
                sb[(2 * j + 1) * 97 + lane]      = p.y;
                p = upk(a1[j]);
                sb[(2 * j) * 97 + 32 + lane]     = p.x;
                sb[(2 * j + 1) * 97 + 32 + lane] = p.y;
                p = upk(a2[j]);
                sb[(2 * j) * 97 + 64 + lane]     = p.x;
                sb[(2 * j + 1) * 97 + 64 + lane] = p.y;
            }
        }
        __syncthreads();
        // Stage 2: warps 4-7 add their partials into the same slots.
        if (warp >= 4) {
#pragma unroll
            for (int j = 0; j < 4; j++) {
                float2 p;
                p = upk(a0[j]);
                sb[(2 * j) * 97 + lane]          += p.x;
                sb[(2 * j + 1) * 97 + lane]      += p.y;
                p = upk(a1[j]);
                sb[(2 * j) * 97 + 32 + lane]     += p.x;
                sb[(2 * j + 1) * 97 + 32 + lane] += p.y;
                p = upk(a2[j]);
                sb[(2 * j) * 97 + 64 + lane]     += p.x;
                sb[(2 * j + 1) * 97 + 64 + lane] += p.y;
            }
        }
        __syncthreads();

        // Epilogue: sum 4 k-chunk partials per gate; b = warp, il = lane.
        float ghr = bh_r, ghz = bh_z, ghn = bh_n;
#pragma unroll
        for (int q = 0; q < 4; q++) {
            const float* e = sgh + q * 776 + warp * 97;
            ghr += e[il];
            ghz += e[32 + il];
            ghn += e[64 + il];
        }

        const float rg = 1.f / (1.f + __expf(-(gir + ghr)));
        const float zg = 1.f / (1.f + __expf(-(giz + ghz)));
        const float ng = tanhf(gin + rg * ghn);
        const float hn = (1.f - zg) * ng + zg * hold;
        hold = hn;

        __stcg(&hdst[iglob * 8 + warp], hn);
        __syncthreads();
        __threadfence();
        if (tid == 0) flags[sl * 8] = base + 2 + (unsigned)s;

        // Off critical path: output stores.
        out[((size_t)s * B_ + bglob) * (2 * H_) + dir * H_ + iglob] = hn;
        if (write_states && s == T_ - 1)
            out[(size_t)T_ * B_ * 2 * H_ + (size_t)(dir * B_ + bglob) * H_ + iglob] = hn;
    }
}

// ---------------------------------------------------------------------------
extern "C" void kernel_launch(void* const* d_in, const int* in_sizes, int n_in,
                              void* d_out, int out_size)
{
    const float* x    = (const float*)d_in[0];
    const float* h0   = (const float*)d_in[1];
    const float* wihf = (const float*)d_in[2];
    const float* bihf = (const float*)d_in[3];
    const float* whhf = (const float*)d_in[4];
    const float* bhhf = (const float*)d_in[5];
    const float* wihr = (const float*)d_in[6];
    const float* bihr = (const float*)d_in[7];
    const float* whhr = (const float*)d_in[8];
    const float* bhhr = (const float*)d_in[9];
    float* out = (float*)d_out;

    cudaFuncSetAttribute(gru_rec, cudaFuncAttributeMaxDynamicSharedMemorySize, SMEM_REC);

    dim3 g1(G_ / 128, (T_ * B_) / 128, 2);
    gi_gemm<<<g1, 256>>>(x, wihf, bihf, wihr, bihr);

    gru_rec<<<128, 256, SMEM_REC>>>(h0, whhf, bhhf, whhr, bhhr, out, out_size);
}